// round 6
// baseline (speedup 1.0000x reference)
#include <cuda_runtime.h>

#define NROWS  65536
#define KCODES 1024
#define DDIM   256

#define TN 128          // rows per CTA tile
#define TK 128          // codes per K-chunk
#define DC 16           // D-slice per smem stage
#define NSTEPS (DDIM / DC)
#define TNP (TN + 4)    // smem padding to reduce bank conflicts (keeps 16B alignment)
#define TKP (TK + 4)

__device__ float  g_rowA[NROWS];   // ||x_n||^2
__device__ float  g_colB[KCODES];  // ||e_k||^2
__device__ int    g_idx[NROWS];
__device__ double g_part[1024];

// ---------------------------------------------------------------------------
// squared row norms: one warp per row (coalesced), fp32 fma + butterfly reduce
// which == 0 -> write g_rowA,  which == 1 -> write g_colB
// ---------------------------------------------------------------------------
__global__ void vq_sqnorm_kernel(const float* __restrict__ src, int nrows, int which)
{
    int gw   = (blockIdx.x * blockDim.x + threadIdx.x) >> 5;
    int lane = threadIdx.x & 31;
    if (gw >= nrows) return;
    const float* p = src + (size_t)gw * DDIM;
    float s = 0.f;
#pragma unroll
    for (int i = 0; i < DDIM / 32; ++i) {
        float v = p[i * 32 + lane];
        s = fmaf(v, v, s);
    }
#pragma unroll
    for (int m = 16; m > 0; m >>= 1)
        s += __shfl_xor_sync(0xffffffffu, s, m);
    if (lane == 0) {
        if (which == 0) g_rowA[gw] = s;
        else            g_colB[gw] = s;
    }
}

// ---------------------------------------------------------------------------
// fused GEMM + argmin:
//   dist[n,k] = round( round(A_n + b_k) - 2 * dot(x_n, e_k) )   (fp32, matches ref)
//   idx[n] = argmin_k dist  (tie -> smallest k, matches jnp.argmin)
// CTA: 256 threads as (tx=16 code-groups, ty=16 row-groups), 8x8 register tile.
// Tile: 128 rows x 128 codes, K-chunks of 128 over 1024 codes,
// D staged through double-buffered smem in slices of 16.
// ---------------------------------------------------------------------------
__global__ __launch_bounds__(256) void vq_argmin_kernel(
    const float* __restrict__ x, const float* __restrict__ emb)
{
    __shared__ __align__(16) float sx[2][DC][TNP];
    __shared__ __align__(16) float se[2][DC][TKP];

    const int tid = threadIdx.x;
    const int tx  = tid & 15;
    const int ty  = tid >> 4;
    const int r0  = blockIdx.x * TN;

    float rowA[8];
#pragma unroll
    for (int i = 0; i < 8; ++i) rowA[i] = g_rowA[r0 + ty * 8 + i];

    float bestv[8];
    int   besti[8];
#pragma unroll
    for (int i = 0; i < 8; ++i) { bestv[i] = 3.402823466e38f; besti[i] = 0; }

    float4 vx[2], ve[2];

#pragma unroll 1
    for (int kc = 0; kc < KCODES; kc += TK) {
        float acc[8][8];
#pragma unroll
        for (int i = 0; i < 8; ++i)
#pragma unroll
            for (int j = 0; j < 8; ++j) acc[i][j] = 0.f;

        // ---- load first D-slice ----
        {
            const int dbase = 0;
#pragma unroll
            for (int s = 0; s < 2; ++s) {
                int f = tid + s * 256;          // 0..511
                int row = f >> 2;               // 0..127
                int seg = f & 3;                // 4 floats each
                vx[s] = *(const float4*)(x   + (size_t)(r0 + row) * DDIM + dbase + seg * 4);
                ve[s] = *(const float4*)(emb + (size_t)(kc + row) * DDIM + dbase + seg * 4);
            }
        }
        __syncthreads();   // previous chunk's readers done before we overwrite smem
        int buf = 0;
#pragma unroll
        for (int s = 0; s < 2; ++s) {
            int f = tid + s * 256;
            int row = f >> 2, seg = f & 3;
            sx[buf][seg*4+0][row] = vx[s].x; sx[buf][seg*4+1][row] = vx[s].y;
            sx[buf][seg*4+2][row] = vx[s].z; sx[buf][seg*4+3][row] = vx[s].w;
            se[buf][seg*4+0][row] = ve[s].x; se[buf][seg*4+1][row] = ve[s].y;
            se[buf][seg*4+2][row] = ve[s].z; se[buf][seg*4+3][row] = ve[s].w;
        }

#pragma unroll 1
        for (int step = 0; step < NSTEPS; ++step) {
            __syncthreads();   // current smem buffer is fully populated

            if (step + 1 < NSTEPS) {             // prefetch next slice to regs
                int dbase = (step + 1) * DC;
#pragma unroll
                for (int s = 0; s < 2; ++s) {
                    int f = tid + s * 256;
                    int row = f >> 2, seg = f & 3;
                    vx[s] = *(const float4*)(x   + (size_t)(r0 + row) * DDIM + dbase + seg * 4);
                    ve[s] = *(const float4*)(emb + (size_t)(kc + row) * DDIM + dbase + seg * 4);
                }
            }

            // ---- compute on smem[buf] ----
#pragma unroll
            for (int dd = 0; dd < DC; ++dd) {
                float xf[8], ef[8];
                *(float4*)&xf[0] = *(const float4*)&sx[buf][dd][ty * 8];
                *(float4*)&xf[4] = *(const float4*)&sx[buf][dd][ty * 8 + 4];
                *(float4*)&ef[0] = *(const float4*)&se[buf][dd][tx * 8];
                *(float4*)&ef[4] = *(const float4*)&se[buf][dd][tx * 8 + 4];
#pragma unroll
                for (int i = 0; i < 8; ++i)
#pragma unroll
                    for (int j = 0; j < 8; ++j)
                        acc[i][j] = fmaf(xf[i], ef[j], acc[i][j]);
            }

            if (step + 1 < NSTEPS) {
                __syncthreads();                 // everyone done reading buf^1's old data
                int nb = buf ^ 1;
#pragma unroll
                for (int s = 0; s < 2; ++s) {
                    int f = tid + s * 256;
                    int row = f >> 2, seg = f & 3;
                    sx[nb][seg*4+0][row] = vx[s].x; sx[nb][seg*4+1][row] = vx[s].y;
                    sx[nb][seg*4+2][row] = vx[s].z; sx[nb][seg*4+3][row] = vx[s].w;
                    se[nb][seg*4+0][row] = ve[s].x; se[nb][seg*4+1][row] = ve[s].y;
                    se[nb][seg*4+2][row] = ve[s].z; se[nb][seg*4+3][row] = ve[s].w;
                }
                buf = nb;
            }
        }

        // ---- epilogue for this K-chunk (replicates reference fp32 rounding) ----
        float bB[8];
        *(float4*)&bB[0] = *(const float4*)&g_colB[kc + tx * 8];
        *(float4*)&bB[4] = *(const float4*)&g_colB[kc + tx * 8 + 4];
#pragma unroll
        for (int i = 0; i < 8; ++i) {
#pragma unroll
            for (int j = 0; j < 8; ++j) {
                float t1   = rowA[i] + bB[j];            // round(A + b) -- the delta grid
                float dist = fmaf(-2.f, acc[i][j], t1);  // == round(t1 - 2*dot), 2*dot exact
                if (dist < bestv[i]) { bestv[i] = dist; besti[i] = kc + tx * 8 + j; }
            }
        }
    }

    // cross-thread argmin over the 16 tx lanes (same warp, 16-lane groups)
#pragma unroll
    for (int i = 0; i < 8; ++i) {
        float v  = bestv[i];
        int   bi = besti[i];
#pragma unroll
        for (int m = 8; m > 0; m >>= 1) {
            float ov = __shfl_xor_sync(0xffffffffu, v,  m);
            int   oi = __shfl_xor_sync(0xffffffffu, bi, m);
            if (ov < v || (ov == v && oi < bi)) { v = ov; bi = oi; }
        }
        if (tx == 0) g_idx[r0 + ty * 8 + i] = bi;
    }
}

// ---------------------------------------------------------------------------
// gather + straight-through output + per-block MSE partials (fp32 squares,
// double accumulation; deterministic).
// out[e] = x[e] + (emb[idx][e] - x[e])   (both roundings replicate reference)
// ---------------------------------------------------------------------------
__global__ void vq_gather_kernel(const float* __restrict__ x,
                                 const float* __restrict__ emb,
                                 float* __restrict__ out)
{
    __shared__ double sred[256];
    const float4* x4 = (const float4*)x;
    const float4* e4 = (const float4*)emb;
    float4*       o4 = (float4*)out;

    double s = 0.0;
    int base = blockIdx.x * 4096;               // 4096 float4 per block
#pragma unroll 4
    for (int it = 0; it < 16; ++it) {
        int f = base + it * 256 + threadIdx.x;
        int n = f >> 6;                          // 64 float4 per row
        int c = g_idx[n];
        float4 q  = e4[c * 64 + (f & 63)];
        float4 xv = x4[f];
        float t0 = q.x - xv.x, t1 = q.y - xv.y, t2 = q.z - xv.z, t3 = q.w - xv.w;
        float4 o = make_float4(xv.x + t0, xv.y + t1, xv.z + t2, xv.w + t3);
        o4[f] = o;
        s += (double)(t0 * t0) + (double)(t1 * t1) + (double)(t2 * t2) + (double)(t3 * t3);
    }
    sred[threadIdx.x] = s;
    __syncthreads();
#pragma unroll
    for (int m = 128; m > 0; m >>= 1) {
        if (threadIdx.x < m) sred[threadIdx.x] += sred[threadIdx.x + m];
        __syncthreads();
    }
    if (threadIdx.x == 0) g_part[blockIdx.x] = sred[0];
}

// loss = m + 0.25*m  with m = mean((q - x)^2); deterministic serial combine.
__global__ void vq_finalize_kernel(float* __restrict__ out, int write_loss)
{
    if (threadIdx.x == 0 && blockIdx.x == 0) {
        double s = 0.0;
        for (int i = 0; i < 1024; ++i) s += g_part[i];
        float m = (float)(s / ((double)NROWS * (double)DDIM));
        if (write_loss) out[(size_t)NROWS * DDIM] = m + 0.25f * m;
    }
}

// ---------------------------------------------------------------------------
extern "C" void kernel_launch(void* const* d_in, const int* in_sizes, int n_in,
                              void* d_out, int out_size)
{
    const float* x   = (const float*)d_in[0];
    const float* emb = (const float*)d_in[1];
    // defensive: if metadata order is swapped, fix it by size
    if (n_in >= 2 && in_sizes[0] == KCODES * DDIM && in_sizes[1] == NROWS * DDIM) {
        const float* t = x; x = emb; emb = t;
    }
    float* out = (float*)d_out;

    vq_sqnorm_kernel<<<(NROWS * 32) / 256, 256>>>(x,   NROWS,  0);
    vq_sqnorm_kernel<<<(KCODES * 32) / 256, 256>>>(emb, KCODES, 1);
    vq_argmin_kernel<<<NROWS / TN, 256>>>(x, emb);
    vq_gather_kernel<<<1024, 256>>>(x, emb, out);
    vq_finalize_kernel<<<1, 32>>>(out, out_size > NROWS * DDIM ? 1 : 0);
}